// round 13
// baseline (speedup 1.0000x reference)
#include <cuda_runtime.h>
#include <cuda_fp16.h>

#define NMAX 50016
#define EMAX 1600000
#define NEG 0.2f
#define NINF __int_as_float(0xff800000)

// ---------------- scratch ----------------
__device__ __align__(256) __half g_h1[NMAX * 64];    // layer1 features (fp16 values)
__device__ __align__(256) float g_g2[NMAX * 32];     // layer2 features (mu|ls), fp32
__device__ float g_a1s[NMAX * 2], g_a1d[NMAX * 2];
__device__ float g_a2s[NMAX * 2], g_a2d[NMAX * 2];
__device__ float g_A1[2], g_A2[2];                   // global maxima of a_src per head
__device__ __align__(16) int g_deg[NMAX];
__device__ int g_cur[NMAX];
__device__ int g_off[NMAX + 1];
__device__ int g_bsum[64], g_boff[64];
__device__ int g_csr[EMAX];
__device__ int g_is64;
__device__ int g_scan_done;

// ---------------- helpers ----------------
__device__ __forceinline__ void atomicMaxFloat(float* addr, float v) {
    if (v >= 0.f) atomicMax((int*)addr, __float_as_int(v));
    else          atomicMin((unsigned int*)addr, __float_as_uint(v));
}
__device__ __forceinline__ float lrelu(float v) { return v > 0.f ? v : NEG * v; }

__device__ __forceinline__ void load_sd(const void* ei, int E, int t, int& s, int& d) {
    if (g_is64) {
        const long long* p = (const long long*)ei;
        s = (int)p[t]; d = (int)p[(long long)E + t];
    } else {
        const int* p = (const int*)ei;
        s = p[t]; d = p[E + t];
    }
}

// load 4 fp16 h1 values (cols 4l..4l+3 of node row) as 2 float2
__device__ __forceinline__ void load_h1_4(int node, int l, float2& f01, float2& f23) {
    uint2 u = ((const uint2*)g_h1)[(size_t)node * 16 + l];
    f01 = __half22float2(*(const __half2*)&u.x);
    f23 = __half22float2(*(const __half2*)&u.y);
}

// ---------------- dtype detect + extrema/counter init (1 block) ----------------
__global__ void k_detect(const int* ei32, int E) {
    __shared__ int any;
    if (threadIdx.x == 0) any = 0;
    __syncthreads();
    int n = min(2 * E, 4096);
    for (int j = threadIdx.x; 2 * j + 1 < n; j += blockDim.x)
        if (ei32[2 * j + 1] != 0) any = 1;
    __syncthreads();
    if (threadIdx.x == 0) {
        g_is64 = (any == 0) ? 1 : 0;
        g_scan_done = 0;
    }
    if (threadIdx.x < 2) { g_A1[threadIdx.x] = NINF; g_A2[threadIdx.x] = NINF; }
}

// ---------------- CSR build ----------------
__global__ void k_hist(const void* __restrict__ ei, int E) {
    int t = blockIdx.x * blockDim.x + threadIdx.x;
    if (t >= E) return;
    int d;
    if (g_is64) d = (int)((const long long*)ei)[(long long)E + t];
    else        d = ((const int*)ei)[E + t];
    atomicAdd(&g_deg[d], 1);
}

// block-local exclusive scan (g_off/g_cur) + last-block does the block-base scan
__global__ __launch_bounds__(256) void k_scan(int N, int E) {
    int t = threadIdx.x, b = blockIdx.x;
    int base = b * 1024 + t * 4;
    int v0 = 0, v1 = 0, v2 = 0, v3 = 0;
    if (base + 3 < N) {
        int4 q = *(const int4*)&g_deg[base];
        v0 = q.x; v1 = q.y; v2 = q.z; v3 = q.w;
    } else {
        if (base < N)     v0 = g_deg[base];
        if (base + 1 < N) v1 = g_deg[base + 1];
        if (base + 2 < N) v2 = g_deg[base + 2];
        if (base + 3 < N) v3 = g_deg[base + 3];
    }
    int s = v0 + v1 + v2 + v3;
    int lane = t & 31, warp = t >> 5;
    int incl = s;
    #pragma unroll
    for (int o = 1; o < 32; o <<= 1) {
        int nv = __shfl_up_sync(~0u, incl, o);
        if (lane >= o) incl += nv;
    }
    __shared__ int wsum[8];
    __shared__ int lastdone;
    if (lane == 31) wsum[warp] = incl;
    __syncthreads();
    if (t == 0) {
        int run = 0;
        #pragma unroll
        for (int w = 0; w < 8; w++) { int x = wsum[w]; wsum[w] = run; run += x; }
        g_bsum[b] = run;
    }
    __syncthreads();
    int excl = incl - s + wsum[warp];
    if (base < N)     { g_off[base]     = excl;                g_cur[base]     = excl; }
    if (base + 1 < N) { g_off[base + 1] = excl + v0;           g_cur[base + 1] = excl + v0; }
    if (base + 2 < N) { g_off[base + 2] = excl + v0 + v1;      g_cur[base + 2] = excl + v0 + v1; }
    if (base + 3 < N) { g_off[base + 3] = excl + v0 + v1 + v2; g_cur[base + 3] = excl + v0 + v1 + v2; }

    // last-finished block performs the block-base exclusive scan (former k_scan2)
    __threadfence();
    if (t == 0) lastdone = (atomicAdd(&g_scan_done, 1) == gridDim.x - 1) ? 1 : 0;
    __syncthreads();
    if (lastdone) {
        __shared__ int sm2[64];
        int B = gridDim.x;
        if (t < 64) sm2[t] = (t < B) ? g_bsum[t] : 0;
        __syncthreads();
        if (t == 0) {
            int run = 0;
            for (int i = 0; i < B; i++) { int x = sm2[i]; sm2[i] = run; run += x; }
            g_off[N] = E - sm2[N >> 10];
        }
        __syncthreads();
        if (t < B) g_boff[t] = sm2[t];
    }
}

__global__ void k_scatter(const void* __restrict__ ei, int E) {
    int t = blockIdx.x * blockDim.x + threadIdx.x;
    if (t >= E) return;
    int s, d;
    load_sd(ei, E, t, s, d);
    int pos = atomicAdd(&g_cur[d], 1) + g_boff[d >> 10];
    g_csr[pos] = s;
}

// ---------------- GEMM1 + attention scalars + global max A1 ----------------
__global__ __launch_bounds__(256) void k_gemm1(
    const float* __restrict__ x, const float* __restrict__ W1,
    const float* __restrict__ att_s, const float* __restrict__ att_d, int N)
{
    __shared__ float xt[128][68];
    __shared__ float Ws[128][64];
    __shared__ float sA[2];
    int tid = threadIdx.x;
    int tx = tid & 15, ty = tid >> 4;
    int row0 = blockIdx.x * 64;

    if (tid < 2) sA[tid] = NINF;
    for (int i = tid; i < 128 * 64; i += 256) Ws[i >> 6][i & 63] = W1[i];

    int lr = tid >> 2;
    int kc = (tid & 3) * 32;
    int grow = row0 + lr;
    if (grow < N) {
        const float4* xrow = (const float4*)(x + (size_t)grow * 128);
        #pragma unroll
        for (int i = 0; i < 8; i++) {
            float4 v = xrow[(kc >> 2) + i];
            int k = kc + i * 4;
            xt[k][lr] = v.x; xt[k + 1][lr] = v.y; xt[k + 2][lr] = v.z; xt[k + 3][lr] = v.w;
        }
    } else {
        #pragma unroll
        for (int i = 0; i < 8; i++) {
            int k = kc + i * 4;
            xt[k][lr] = 0.f; xt[k + 1][lr] = 0.f; xt[k + 2][lr] = 0.f; xt[k + 3][lr] = 0.f;
        }
    }
    __syncthreads();

    float acc[4][4];
    #pragma unroll
    for (int i = 0; i < 4; i++)
        #pragma unroll
        for (int j = 0; j < 4; j++) acc[i][j] = 0.f;

    #pragma unroll 4
    for (int k = 0; k < 128; k++) {
        float4 xv = *(const float4*)&xt[k][ty * 4];
        float4 wv = *(const float4*)&Ws[k][tx * 4];
        float xa[4] = {xv.x, xv.y, xv.z, xv.w};
        float wa[4] = {wv.x, wv.y, wv.z, wv.w};
        #pragma unroll
        for (int i = 0; i < 4; i++)
            #pragma unroll
            for (int j = 0; j < 4; j++) acc[i][j] += xa[i] * wa[j];
    }

    float ps[4], pd[4];
    #pragma unroll
    for (int i = 0; i < 4; i++) {
        ps[i] = 0.f; pd[i] = 0.f;
        #pragma unroll
        for (int j = 0; j < 4; j++) {
            int c = tx * 4 + j;
            ps[i] += acc[i][j] * att_s[c];
            pd[i] += acc[i][j] * att_d[c];
        }
    }
    #pragma unroll
    for (int i = 0; i < 4; i++) {
        int r = row0 + ty * 4 + i;
        if (r < N) {
            __half2 h01 = __float22half2_rn(make_float2(acc[i][0], acc[i][1]));
            __half2 h23 = __float22half2_rn(make_float2(acc[i][2], acc[i][3]));
            uint2 u;
            u.x = *(const unsigned int*)&h01;
            u.y = *(const unsigned int*)&h23;
            ((uint2*)g_h1)[(size_t)r * 16 + tx] = u;
        }
    }
    #pragma unroll
    for (int o = 1; o < 8; o <<= 1) {
        #pragma unroll
        for (int i = 0; i < 4; i++) {
            ps[i] += __shfl_xor_sync(0xffffffffu, ps[i], o);
            pd[i] += __shfl_xor_sync(0xffffffffu, pd[i], o);
        }
    }
    if ((tx & 7) == 0) {
        int head = tx >> 3;
        #pragma unroll
        for (int i = 0; i < 4; i++) {
            int r = row0 + ty * 4 + i;
            if (r < N) {
                g_a1s[r * 2 + head] = ps[i];
                g_a1d[r * 2 + head] = pd[i];
                atomicMaxFloat(&sA[head], ps[i]);
            }
        }
    }
    __syncthreads();
    if (tid < 2) atomicMaxFloat(&g_A1[tid], sA[tid]);
}

// ---------------- layer1 aggregate + normalize + relu + GEMM2 + att2 (fused) ----------
__global__ __launch_bounds__(256) void k_acc1(
    const float* __restrict__ Wmu, const float* __restrict__ Wls,
    const float* __restrict__ b1,
    const float* __restrict__ asmu, const float* __restrict__ admu,
    const float* __restrict__ asls, const float* __restrict__ adls, int N)
{
    __shared__ float Ws[2][1040];
    __shared__ float h2s[8][64];
    __shared__ float att[4][16];
    __shared__ float b1s[64];
    __shared__ float blkmax[2];
    int tid = threadIdx.x;
    for (int i = tid; i < 1024; i += 256) { Ws[0][i] = Wmu[i]; Ws[1][i] = Wls[i]; }
    if (tid < 16) {
        att[0][tid] = asmu[tid]; att[1][tid] = admu[tid];
        att[2][tid] = asls[tid]; att[3][tid] = adls[tid];
    }
    if (tid < 64) b1s[tid] = b1[tid];
    if (tid < 2) blkmax[tid] = NINF;
    __syncthreads();

    int lane = tid & 31, warp = tid >> 5;
    int group = lane >> 4, l = lane & 15, head = l >> 3;
    int sel = lane >> 4, col = lane & 15;
    float A = g_A1[head];
    float localmax = NINF;
    int nwarps = gridDim.x * 8;

    for (int node = blockIdx.x * 8 + warp; node < N; node += nwarps) {
        __syncwarp();
        float adn = g_a1d[node * 2 + head];
        float m = lrelu(A + adn);
        float4 acc = {0.f, 0.f, 0.f, 0.f};
        float den = 0.f;
        if (group == 0) {   // self loop
            float e = lrelu(g_a1s[node * 2 + head] + adn);
            float ex = __expf(e - m);
            float2 f01, f23;
            load_h1_4(node, l, f01, f23);
            acc.x = ex * f01.x; acc.y = ex * f01.y; acc.z = ex * f23.x; acc.w = ex * f23.y;
            den = ex;
        }
        int beg = g_off[node] + g_boff[node >> 10];
        int end = g_off[node + 1] + g_boff[(node + 1) >> 10];
        int i = beg + group;
        int sn = (i < end) ? g_csr[i] : 0;
        while (i < end) {
            int s = sn;
            int inext = i + 2;
            if (inext < end) sn = g_csr[inext];
            float e = lrelu(g_a1s[s * 2 + head] + adn);
            float ex = __expf(e - m);
            float2 f01, f23;
            load_h1_4(s, l, f01, f23);
            acc.x += ex * f01.x; acc.y += ex * f01.y; acc.z += ex * f23.x; acc.w += ex * f23.y;
            den += ex;
            i = inext;
        }
        acc.x += __shfl_xor_sync(~0u, acc.x, 16);
        acc.y += __shfl_xor_sync(~0u, acc.y, 16);
        acc.z += __shfl_xor_sync(~0u, acc.z, 16);
        acc.w += __shfl_xor_sync(~0u, acc.w, 16);
        den   += __shfl_xor_sync(~0u, den, 16);
        if (group == 0) {
            float inv = 1.f / (den + 1e-16f);
            float v0 = fmaxf(acc.x * inv + b1s[4 * l + 0], 0.f);
            float v1 = fmaxf(acc.y * inv + b1s[4 * l + 1], 0.f);
            float v2 = fmaxf(acc.z * inv + b1s[4 * l + 2], 0.f);
            float v3 = fmaxf(acc.w * inv + b1s[4 * l + 3], 0.f);
            *(float4*)&h2s[warp][4 * l] = make_float4(v0, v1, v2, v3);
        }
        __syncwarp();
        const float* W = Ws[sel];
        float a = 0.f;
        #pragma unroll
        for (int k = 0; k < 64; k++) a += h2s[warp][k] * W[k * 16 + col];
        g_g2[(size_t)node * 32 + lane] = a;
        float ps = a * att[sel * 2 + 0][col];
        float pd = a * att[sel * 2 + 1][col];
        #pragma unroll
        for (int o = 8; o > 0; o >>= 1) {
            ps += __shfl_xor_sync(~0u, ps, o);
            pd += __shfl_xor_sync(~0u, pd, o);
        }
        if (col == 0) {
            g_a2s[node * 2 + sel] = ps;
            g_a2d[node * 2 + sel] = pd;
            localmax = fmaxf(localmax, ps);
        }
    }
    if (col == 0) atomicMaxFloat(&blkmax[sel], localmax);
    __syncthreads();
    if (tid < 2) atomicMaxFloat(&g_A2[tid], blkmax[tid]);
}

// ---------------- layer2 aggregate + normalize + bias + output (fused) ----------------
__global__ __launch_bounds__(256) void k_acc2(
    const float* __restrict__ bmu, const float* __restrict__ bls,
    float* __restrict__ out, int N)
{
    int tid = threadIdx.x, lane = tid & 31, warp = tid >> 5;
    int group = lane >> 3, l = lane & 7, sel = l >> 2;
    float A = g_A2[sel];
    int nwarps = gridDim.x * 8;
    for (int node = blockIdx.x * 8 + warp; node < N; node += nwarps) {
        float adn = g_a2d[node * 2 + sel];
        float m = lrelu(A + adn);
        float4 acc = {0.f, 0.f, 0.f, 0.f};
        float den = 0.f;
        if (group == 0) {   // self loop
            float e = lrelu(g_a2s[node * 2 + sel] + adn);
            float ex = __expf(e - m);
            float4 g = ((const float4*)g_g2)[(size_t)node * 8 + l];
            acc.x = ex * g.x; acc.y = ex * g.y; acc.z = ex * g.z; acc.w = ex * g.w;
            den = ex;
        }
        int beg = g_off[node] + g_boff[node >> 10];
        int end = g_off[node + 1] + g_boff[(node + 1) >> 10];
        int i = beg + group;
        int sn = (i < end) ? g_csr[i] : 0;
        while (i < end) {
            int s = sn;
            int inext = i + 4;
            if (inext < end) sn = g_csr[inext];
            float e = lrelu(g_a2s[s * 2 + sel] + adn);
            float ex = __expf(e - m);
            float4 g = ((const float4*)g_g2)[(size_t)s * 8 + l];
            acc.x += ex * g.x; acc.y += ex * g.y; acc.z += ex * g.z; acc.w += ex * g.w;
            den += ex;
            i = inext;
        }
        #pragma unroll
        for (int o = 8; o <= 16; o <<= 1) {
            acc.x += __shfl_xor_sync(~0u, acc.x, o);
            acc.y += __shfl_xor_sync(~0u, acc.y, o);
            acc.z += __shfl_xor_sync(~0u, acc.z, o);
            acc.w += __shfl_xor_sync(~0u, acc.w, o);
            den   += __shfl_xor_sync(~0u, den, o);
        }
        if (group == 0) {
            float inv = 1.f / (den + 1e-16f);
            float4 v;
            v.x = acc.x * inv; v.y = acc.y * inv; v.z = acc.z * inv; v.w = acc.w * inv;
            if (sel == 0) {
                float4 bv = ((const float4*)bmu)[l];
                v.x += bv.x; v.y += bv.y; v.z += bv.z; v.w += bv.w;
                ((float4*)out)[(size_t)node * 4 + l] = v;
            } else {
                float4 bv = ((const float4*)bls)[l - 4];
                v.x += bv.x; v.y += bv.y; v.z += bv.z; v.w += bv.w;
                ((float4*)(out + (size_t)N * 16))[(size_t)node * 4 + (l - 4)] = v;
            }
        }
    }
}

// ---------------- launch ----------------
static void* g_degPtr = 0;

extern "C" void kernel_launch(void* const* d_in, const int* in_sizes, int n_in,
                              void* d_out, int out_size) {
    const float* x    = (const float*)d_in[0];
    const void*  ei   = d_in[1];
    const float* W1   = (const float*)d_in[2];
    const float* as1  = (const float*)d_in[3];
    const float* ad1  = (const float*)d_in[4];
    const float* b1   = (const float*)d_in[5];
    const float* Wmu  = (const float*)d_in[6];
    const float* asmu = (const float*)d_in[7];
    const float* admu = (const float*)d_in[8];
    const float* bmu  = (const float*)d_in[9];
    const float* Wls  = (const float*)d_in[10];
    const float* asls = (const float*)d_in[11];
    const float* adls = (const float*)d_in[12];
    const float* bls  = (const float*)d_in[13];
    float* out = (float*)d_out;

    int N = in_sizes[0] / 128;
    int E = in_sizes[1] / 2;
    int B1 = (N + 1023) / 1024;

    if (!g_degPtr) cudaGetSymbolAddress(&g_degPtr, g_deg);

    cudaMemsetAsync(g_degPtr, 0, (size_t)N * sizeof(int), 0);
    k_detect<<<1, 256>>>((const int*)ei, E);
    k_hist<<<(E + 255) / 256, 256>>>(ei, E);
    k_gemm1<<<(N + 63) / 64, 256>>>(x, W1, as1, ad1, N);
    k_scan<<<B1, 256>>>(N, E);
    k_scatter<<<(E + 255) / 256, 256>>>(ei, E);
    k_acc1<<<1184, 256>>>(Wmu, Wls, b1, asmu, admu, asls, adls, N);
    k_acc2<<<1184, 256>>>(bmu, bls, out, N);
}

// round 14
// speedup vs baseline: 1.1072x; 1.1072x over previous
#include <cuda_runtime.h>
#include <cuda_fp16.h>

#define NMAX 50016
#define EMAX 1600000
#define NEG 0.2f
#define NINF __int_as_float(0xff800000)

// ---------------- scratch ----------------
__device__ __align__(256) __half g_h1[NMAX * 64];    // layer1 features (fp16 values)
__device__ __align__(256) float g_g2[NMAX * 32];     // layer2 features (mu|ls), fp32
__device__ float g_a1s[NMAX * 2], g_a1d[NMAX * 2];
__device__ float g_a2s[NMAX * 2], g_a2d[NMAX * 2];
__device__ float g_A1[2], g_A2[2];                   // global maxima of a_src per head
__device__ __align__(16) int g_deg[NMAX];
__device__ int g_cur[NMAX];
__device__ int g_off[NMAX + 1];
__device__ int g_bsum[64], g_boff[64];
__device__ int g_csr[EMAX];
__device__ int g_is64;

// ---------------- helpers ----------------
__device__ __forceinline__ void atomicMaxFloat(float* addr, float v) {
    if (v >= 0.f) atomicMax((int*)addr, __float_as_int(v));
    else          atomicMin((unsigned int*)addr, __float_as_uint(v));
}
__device__ __forceinline__ float lrelu(float v) { return v > 0.f ? v : NEG * v; }

__device__ __forceinline__ void load_sd(const void* ei, int E, int t, int& s, int& d) {
    if (g_is64) {
        const long long* p = (const long long*)ei;
        s = (int)p[t]; d = (int)p[(long long)E + t];
    } else {
        const int* p = (const int*)ei;
        s = p[t]; d = p[E + t];
    }
}

// load 4 fp16 h1 values (cols 4l..4l+3 of node row) as 2 float2
__device__ __forceinline__ void load_h1_4(int node, int l, float2& f01, float2& f23) {
    uint2 u = ((const uint2*)g_h1)[(size_t)node * 16 + l];
    f01 = __half22float2(*(const __half2*)&u.x);
    f23 = __half22float2(*(const __half2*)&u.y);
}

// ---------------- init + dtype detect ----------------
__global__ void k_init(const int* ei32, int E, int N) {
    int i = blockIdx.x * blockDim.x + threadIdx.x;
    if (i < N) g_deg[i] = 0;
    if (i < 2) { g_A1[i] = NINF; g_A2[i] = NINF; }
    if (blockIdx.x == 0) {
        __shared__ int any;
        if (threadIdx.x == 0) any = 0;
        __syncthreads();
        int n = min(2 * E, 4096);
        for (int j = threadIdx.x; 2 * j + 1 < n; j += blockDim.x)
            if (ei32[2 * j + 1] != 0) any = 1;
        __syncthreads();
        if (threadIdx.x == 0) g_is64 = (any == 0) ? 1 : 0;
    }
}

// ---------------- CSR build ----------------
__global__ void k_hist(const void* __restrict__ ei, int E) {
    int t = blockIdx.x * blockDim.x + threadIdx.x;
    if (t >= E) return;
    int d;
    if (g_is64) d = (int)((const long long*)ei)[(long long)E + t];
    else        d = ((const int*)ei)[E + t];
    atomicAdd(&g_deg[d], 1);
}

// block-local exclusive scan; writes local offsets to g_off AND g_cur
__global__ void k_scan1(int N) {
    int t = threadIdx.x, b = blockIdx.x;
    int base = b * 1024 + t * 4;
    int v0 = 0, v1 = 0, v2 = 0, v3 = 0;
    if (base + 3 < N) {
        int4 q = *(const int4*)&g_deg[base];
        v0 = q.x; v1 = q.y; v2 = q.z; v3 = q.w;
    } else {
        if (base < N)     v0 = g_deg[base];
        if (base + 1 < N) v1 = g_deg[base + 1];
        if (base + 2 < N) v2 = g_deg[base + 2];
        if (base + 3 < N) v3 = g_deg[base + 3];
    }
    int s = v0 + v1 + v2 + v3;
    int lane = t & 31, warp = t >> 5;
    int incl = s;
    #pragma unroll
    for (int o = 1; o < 32; o <<= 1) {
        int nv = __shfl_up_sync(~0u, incl, o);
        if (lane >= o) incl += nv;
    }
    __shared__ int wsum[8];
    if (lane == 31) wsum[warp] = incl;
    __syncthreads();
    if (t == 0) {
        int run = 0;
        #pragma unroll
        for (int w = 0; w < 8; w++) { int x = wsum[w]; wsum[w] = run; run += x; }
        g_bsum[b] = run;
    }
    __syncthreads();
    int excl = incl - s + wsum[warp];
    if (base < N)     { g_off[base]     = excl;                g_cur[base]     = excl; }
    if (base + 1 < N) { g_off[base + 1] = excl + v0;           g_cur[base + 1] = excl + v0; }
    if (base + 2 < N) { g_off[base + 2] = excl + v0 + v1;      g_cur[base + 2] = excl + v0 + v1; }
    if (base + 3 < N) { g_off[base + 3] = excl + v0 + v1 + v2; g_cur[base + 3] = excl + v0 + v1 + v2; }
}

// block-base exclusive scan
__global__ void k_scan2(int B, int E, int N) {
    __shared__ int sm[64];
    int t = threadIdx.x;
    sm[t] = (t < B) ? g_bsum[t] : 0;
    __syncthreads();
    if (t == 0) {
        int run = 0;
        for (int i = 0; i < B; i++) { int x = sm[i]; sm[i] = run; run += x; }
        g_off[N] = E - sm[N >> 10];
    }
    __syncthreads();
    if (t < B) g_boff[t] = sm[t];
}

__global__ void k_scatter(const void* __restrict__ ei, int E) {
    int t = blockIdx.x * blockDim.x + threadIdx.x;
    if (t >= E) return;
    int s, d;
    load_sd(ei, E, t, s, d);
    int pos = atomicAdd(&g_cur[d], 1) + g_boff[d >> 10];
    g_csr[pos] = s;
}

// ---------------- GEMM1 + attention scalars + global max A1 ----------------
__global__ __launch_bounds__(256) void k_gemm1(
    const float* __restrict__ x, const float* __restrict__ W1,
    const float* __restrict__ att_s, const float* __restrict__ att_d, int N)
{
    __shared__ float xt[128][68];
    __shared__ float Ws[128][64];
    __shared__ float sA[2];
    int tid = threadIdx.x;
    int tx = tid & 15, ty = tid >> 4;
    int row0 = blockIdx.x * 64;

    if (tid < 2) sA[tid] = NINF;
    for (int i = tid; i < 128 * 64; i += 256) Ws[i >> 6][i & 63] = W1[i];

    int lr = tid >> 2;
    int kc = (tid & 3) * 32;
    int grow = row0 + lr;
    if (grow < N) {
        const float4* xrow = (const float4*)(x + (size_t)grow * 128);
        #pragma unroll
        for (int i = 0; i < 8; i++) {
            float4 v = xrow[(kc >> 2) + i];
            int k = kc + i * 4;
            xt[k][lr] = v.x; xt[k + 1][lr] = v.y; xt[k + 2][lr] = v.z; xt[k + 3][lr] = v.w;
        }
    } else {
        #pragma unroll
        for (int i = 0; i < 8; i++) {
            int k = kc + i * 4;
            xt[k][lr] = 0.f; xt[k + 1][lr] = 0.f; xt[k + 2][lr] = 0.f; xt[k + 3][lr] = 0.f;
        }
    }
    __syncthreads();

    float acc[4][4];
    #pragma unroll
    for (int i = 0; i < 4; i++)
        #pragma unroll
        for (int j = 0; j < 4; j++) acc[i][j] = 0.f;

    #pragma unroll 4
    for (int k = 0; k < 128; k++) {
        float4 xv = *(const float4*)&xt[k][ty * 4];
        float4 wv = *(const float4*)&Ws[k][tx * 4];
        float xa[4] = {xv.x, xv.y, xv.z, xv.w};
        float wa[4] = {wv.x, wv.y, wv.z, wv.w};
        #pragma unroll
        for (int i = 0; i < 4; i++)
            #pragma unroll
            for (int j = 0; j < 4; j++) acc[i][j] += xa[i] * wa[j];
    }

    float ps[4], pd[4];
    #pragma unroll
    for (int i = 0; i < 4; i++) {
        ps[i] = 0.f; pd[i] = 0.f;
        #pragma unroll
        for (int j = 0; j < 4; j++) {
            int c = tx * 4 + j;
            ps[i] += acc[i][j] * att_s[c];
            pd[i] += acc[i][j] * att_d[c];
        }
    }
    #pragma unroll
    for (int i = 0; i < 4; i++) {
        int r = row0 + ty * 4 + i;
        if (r < N) {
            __half2 h01 = __float22half2_rn(make_float2(acc[i][0], acc[i][1]));
            __half2 h23 = __float22half2_rn(make_float2(acc[i][2], acc[i][3]));
            uint2 u;
            u.x = *(const unsigned int*)&h01;
            u.y = *(const unsigned int*)&h23;
            ((uint2*)g_h1)[(size_t)r * 16 + tx] = u;
        }
    }
    #pragma unroll
    for (int o = 1; o < 8; o <<= 1) {
        #pragma unroll
        for (int i = 0; i < 4; i++) {
            ps[i] += __shfl_xor_sync(0xffffffffu, ps[i], o);
            pd[i] += __shfl_xor_sync(0xffffffffu, pd[i], o);
        }
    }
    if ((tx & 7) == 0) {
        int head = tx >> 3;
        #pragma unroll
        for (int i = 0; i < 4; i++) {
            int r = row0 + ty * 4 + i;
            if (r < N) {
                g_a1s[r * 2 + head] = ps[i];
                g_a1d[r * 2 + head] = pd[i];
                atomicMaxFloat(&sA[head], ps[i]);
            }
        }
    }
    __syncthreads();
    if (tid < 2) atomicMaxFloat(&g_A1[tid], sA[tid]);
}

// ---------------- layer1 aggregate + normalize + relu + GEMM2 + att2 (fused) ----------
__global__ __launch_bounds__(256) void k_acc1(
    const float* __restrict__ Wmu, const float* __restrict__ Wls,
    const float* __restrict__ b1,
    const float* __restrict__ asmu, const float* __restrict__ admu,
    const float* __restrict__ asls, const float* __restrict__ adls, int N)
{
    __shared__ float Ws[2][1040];
    __shared__ float h2s[8][64];
    __shared__ float att[4][16];
    __shared__ float b1s[64];
    __shared__ float blkmax[2];
    int tid = threadIdx.x;
    for (int i = tid; i < 1024; i += 256) { Ws[0][i] = Wmu[i]; Ws[1][i] = Wls[i]; }
    if (tid < 16) {
        att[0][tid] = asmu[tid]; att[1][tid] = admu[tid];
        att[2][tid] = asls[tid]; att[3][tid] = adls[tid];
    }
    if (tid < 64) b1s[tid] = b1[tid];
    if (tid < 2) blkmax[tid] = NINF;
    __syncthreads();

    int lane = tid & 31, warp = tid >> 5;
    int group = lane >> 4, l = lane & 15, head = l >> 3;
    int sel = lane >> 4, col = lane & 15;
    float A = g_A1[head];
    float localmax = NINF;
    int nwarps = gridDim.x * 8;

    for (int node = blockIdx.x * 8 + warp; node < N; node += nwarps) {
        __syncwarp();
        float adn = g_a1d[node * 2 + head];
        float m = lrelu(A + adn);
        float4 acc = {0.f, 0.f, 0.f, 0.f};
        float den = 0.f;
        if (group == 0) {   // self loop
            float e = lrelu(g_a1s[node * 2 + head] + adn);
            float ex = __expf(e - m);
            float2 f01, f23;
            load_h1_4(node, l, f01, f23);
            acc.x = ex * f01.x; acc.y = ex * f01.y; acc.z = ex * f23.x; acc.w = ex * f23.y;
            den = ex;
        }
        int beg = g_off[node] + g_boff[node >> 10];
        int end = beg + g_deg[node];
        int i = beg + group;
        int sn = (i < end) ? g_csr[i] : 0;
        while (i < end) {
            int s = sn;
            int inext = i + 2;
            if (inext < end) sn = g_csr[inext];
            float e = lrelu(g_a1s[s * 2 + head] + adn);
            float ex = __expf(e - m);
            float2 f01, f23;
            load_h1_4(s, l, f01, f23);
            acc.x += ex * f01.x; acc.y += ex * f01.y; acc.z += ex * f23.x; acc.w += ex * f23.y;
            den += ex;
            i = inext;
        }
        acc.x += __shfl_xor_sync(~0u, acc.x, 16);
        acc.y += __shfl_xor_sync(~0u, acc.y, 16);
        acc.z += __shfl_xor_sync(~0u, acc.z, 16);
        acc.w += __shfl_xor_sync(~0u, acc.w, 16);
        den   += __shfl_xor_sync(~0u, den, 16);
        if (group == 0) {
            float inv = 1.f / (den + 1e-16f);
            float v0 = fmaxf(acc.x * inv + b1s[4 * l + 0], 0.f);
            float v1 = fmaxf(acc.y * inv + b1s[4 * l + 1], 0.f);
            float v2 = fmaxf(acc.z * inv + b1s[4 * l + 2], 0.f);
            float v3 = fmaxf(acc.w * inv + b1s[4 * l + 3], 0.f);
            *(float4*)&h2s[warp][4 * l] = make_float4(v0, v1, v2, v3);
        }
        __syncwarp();
        const float* W = Ws[sel];
        float a = 0.f;
        #pragma unroll
        for (int k = 0; k < 64; k++) a += h2s[warp][k] * W[k * 16 + col];
        g_g2[(size_t)node * 32 + lane] = a;
        float ps = a * att[sel * 2 + 0][col];
        float pd = a * att[sel * 2 + 1][col];
        #pragma unroll
        for (int o = 8; o > 0; o >>= 1) {
            ps += __shfl_xor_sync(~0u, ps, o);
            pd += __shfl_xor_sync(~0u, pd, o);
        }
        if (col == 0) {
            g_a2s[node * 2 + sel] = ps;
            g_a2d[node * 2 + sel] = pd;
            localmax = fmaxf(localmax, ps);
        }
    }
    if (col == 0) atomicMaxFloat(&blkmax[sel], localmax);
    __syncthreads();
    if (tid < 2) atomicMaxFloat(&g_A2[tid], blkmax[tid]);
}

// ---------------- layer2 aggregate + normalize + bias + output (fused) ----------------
__global__ __launch_bounds__(256) void k_acc2(
    const float* __restrict__ bmu, const float* __restrict__ bls,
    float* __restrict__ out, int N)
{
    int tid = threadIdx.x, lane = tid & 31, warp = tid >> 5;
    int group = lane >> 3, l = lane & 7, sel = l >> 2;
    float A = g_A2[sel];
    int nwarps = gridDim.x * 8;
    for (int node = blockIdx.x * 8 + warp; node < N; node += nwarps) {
        float adn = g_a2d[node * 2 + sel];
        float m = lrelu(A + adn);
        float4 acc = {0.f, 0.f, 0.f, 0.f};
        float den = 0.f;
        if (group == 0) {   // self loop
            float e = lrelu(g_a2s[node * 2 + sel] + adn);
            float ex = __expf(e - m);
            float4 g = ((const float4*)g_g2)[(size_t)node * 8 + l];
            acc.x = ex * g.x; acc.y = ex * g.y; acc.z = ex * g.z; acc.w = ex * g.w;
            den = ex;
        }
        int beg = g_off[node] + g_boff[node >> 10];
        int end = beg + g_deg[node];
        int i = beg + group;
        int sn = (i < end) ? g_csr[i] : 0;
        while (i < end) {
            int s = sn;
            int inext = i + 4;
            if (inext < end) sn = g_csr[inext];
            float e = lrelu(g_a2s[s * 2 + sel] + adn);
            float ex = __expf(e - m);
            float4 g = ((const float4*)g_g2)[(size_t)s * 8 + l];
            acc.x += ex * g.x; acc.y += ex * g.y; acc.z += ex * g.z; acc.w += ex * g.w;
            den += ex;
            i = inext;
        }
        #pragma unroll
        for (int o = 8; o <= 16; o <<= 1) {
            acc.x += __shfl_xor_sync(~0u, acc.x, o);
            acc.y += __shfl_xor_sync(~0u, acc.y, o);
            acc.z += __shfl_xor_sync(~0u, acc.z, o);
            acc.w += __shfl_xor_sync(~0u, acc.w, o);
            den   += __shfl_xor_sync(~0u, den, o);
        }
        if (group == 0) {
            float inv = 1.f / (den + 1e-16f);
            float4 v;
            v.x = acc.x * inv; v.y = acc.y * inv; v.z = acc.z * inv; v.w = acc.w * inv;
            if (sel == 0) {
                float4 bv = ((const float4*)bmu)[l];
                v.x += bv.x; v.y += bv.y; v.z += bv.z; v.w += bv.w;
                ((float4*)out)[(size_t)node * 4 + l] = v;
            } else {
                float4 bv = ((const float4*)bls)[l - 4];
                v.x += bv.x; v.y += bv.y; v.z += bv.z; v.w += bv.w;
                ((float4*)(out + (size_t)N * 16))[(size_t)node * 4 + (l - 4)] = v;
            }
        }
    }
}

// ---------------- launch ----------------
extern "C" void kernel_launch(void* const* d_in, const int* in_sizes, int n_in,
                              void* d_out, int out_size) {
    const float* x    = (const float*)d_in[0];
    const void*  ei   = d_in[1];
    const float* W1   = (const float*)d_in[2];
    const float* as1  = (const float*)d_in[3];
    const float* ad1  = (const float*)d_in[4];
    const float* b1   = (const float*)d_in[5];
    const float* Wmu  = (const float*)d_in[6];
    const float* asmu = (const float*)d_in[7];
    const float* admu = (const float*)d_in[8];
    const float* bmu  = (const float*)d_in[9];
    const float* Wls  = (const float*)d_in[10];
    const float* asls = (const float*)d_in[11];
    const float* adls = (const float*)d_in[12];
    const float* bls  = (const float*)d_in[13];
    float* out = (float*)d_out;

    int N = in_sizes[0] / 128;
    int E = in_sizes[1] / 2;
    int B1 = (N + 1023) / 1024;

    k_init<<<(N + 255) / 256, 256>>>((const int*)ei, E, N);
    k_hist<<<(E + 255) / 256, 256>>>(ei, E);
    k_gemm1<<<(N + 63) / 64, 256>>>(x, W1, as1, ad1, N);
    k_scan1<<<B1, 256>>>(N);
    k_scan2<<<1, 64>>>(B1, E, N);
    k_scatter<<<(E + 255) / 256, 256>>>(ei, E);
    k_acc1<<<2368, 256>>>(Wmu, Wls, b1, asmu, admu, asls, adls, N);
    k_acc2<<<2368, 256>>>(bmu, bls, out, N);
}

// round 15
// speedup vs baseline: 1.1075x; 1.0003x over previous
#include <cuda_runtime.h>
#include <cuda_fp16.h>

#define NMAX 50016
#define EMAX 1600000
#define NEG 0.2f
#define NINF __int_as_float(0xff800000)

// ---------------- scratch ----------------
__device__ __align__(256) __half g_h1[NMAX * 64];    // layer1 features (fp16 values)
__device__ __align__(256) float g_g2[NMAX * 32];     // layer2 features (mu|ls), fp32
__device__ float g_a1s[NMAX * 2], g_a1d[NMAX * 2];
__device__ float g_a2s[NMAX * 2], g_a2d[NMAX * 2];
__device__ float g_A1[2], g_A2[2];                   // global maxima of a_src per head
__device__ __align__(16) int g_deg[NMAX];
__device__ int g_cur[NMAX];
__device__ int g_off[NMAX + 1];
__device__ int g_bsum[64], g_boff[64];
__device__ int g_csr[EMAX];
__device__ int g_is64;

// ---------------- helpers ----------------
__device__ __forceinline__ void atomicMaxFloat(float* addr, float v) {
    if (v >= 0.f) atomicMax((int*)addr, __float_as_int(v));
    else          atomicMin((unsigned int*)addr, __float_as_uint(v));
}
__device__ __forceinline__ float lrelu(float v) { return v > 0.f ? v : NEG * v; }

__device__ __forceinline__ void load_sd(const void* ei, int E, int t, int& s, int& d) {
    if (g_is64) {
        const long long* p = (const long long*)ei;
        s = (int)p[t]; d = (int)p[(long long)E + t];
    } else {
        const int* p = (const int*)ei;
        s = p[t]; d = p[E + t];
    }
}

// load 4 fp16 h1 values (cols 4l..4l+3 of node row) as 2 float2
__device__ __forceinline__ void load_h1_4(int node, int l, float2& f01, float2& f23) {
    uint2 u = ((const uint2*)g_h1)[(size_t)node * 16 + l];
    f01 = __half22float2(*(const __half2*)&u.x);
    f23 = __half22float2(*(const __half2*)&u.y);
}

// ---------------- init + dtype detect ----------------
__global__ void k_init(const int* ei32, int E, int N) {
    int i = blockIdx.x * blockDim.x + threadIdx.x;
    if (i < N) g_deg[i] = 0;
    if (i < 2) { g_A1[i] = NINF; g_A2[i] = NINF; }
    if (blockIdx.x == 0) {
        __shared__ int any;
        if (threadIdx.x == 0) any = 0;
        __syncthreads();
        int n = min(2 * E, 4096);
        for (int j = threadIdx.x; 2 * j + 1 < n; j += blockDim.x)
            if (ei32[2 * j + 1] != 0) any = 1;
        __syncthreads();
        if (threadIdx.x == 0) g_is64 = (any == 0) ? 1 : 0;
    }
}

// ---------------- CSR build ----------------
__global__ void k_hist(const void* __restrict__ ei, int E) {
    int t = blockIdx.x * blockDim.x + threadIdx.x;
    if (t >= E) return;
    int d;
    if (g_is64) d = (int)((const long long*)ei)[(long long)E + t];
    else        d = ((const int*)ei)[E + t];
    atomicAdd(&g_deg[d], 1);
}

// block-local exclusive scan; writes local offsets to g_off AND g_cur
__global__ void k_scan1(int N) {
    int t = threadIdx.x, b = blockIdx.x;
    int base = b * 1024 + t * 4;
    int v0 = 0, v1 = 0, v2 = 0, v3 = 0;
    if (base + 3 < N) {
        int4 q = *(const int4*)&g_deg[base];
        v0 = q.x; v1 = q.y; v2 = q.z; v3 = q.w;
    } else {
        if (base < N)     v0 = g_deg[base];
        if (base + 1 < N) v1 = g_deg[base + 1];
        if (base + 2 < N) v2 = g_deg[base + 2];
        if (base + 3 < N) v3 = g_deg[base + 3];
    }
    int s = v0 + v1 + v2 + v3;
    int lane = t & 31, warp = t >> 5;
    int incl = s;
    #pragma unroll
    for (int o = 1; o < 32; o <<= 1) {
        int nv = __shfl_up_sync(~0u, incl, o);
        if (lane >= o) incl += nv;
    }
    __shared__ int wsum[8];
    if (lane == 31) wsum[warp] = incl;
    __syncthreads();
    if (t == 0) {
        int run = 0;
        #pragma unroll
        for (int w = 0; w < 8; w++) { int x = wsum[w]; wsum[w] = run; run += x; }
        g_bsum[b] = run;
    }
    __syncthreads();
    int excl = incl - s + wsum[warp];
    if (base < N)     { g_off[base]     = excl;                g_cur[base]     = excl; }
    if (base + 1 < N) { g_off[base + 1] = excl + v0;           g_cur[base + 1] = excl + v0; }
    if (base + 2 < N) { g_off[base + 2] = excl + v0 + v1;      g_cur[base + 2] = excl + v0 + v1; }
    if (base + 3 < N) { g_off[base + 3] = excl + v0 + v1 + v2; g_cur[base + 3] = excl + v0 + v1 + v2; }
}

// block-base exclusive scan
__global__ void k_scan2(int B, int E, int N) {
    __shared__ int sm[64];
    int t = threadIdx.x;
    sm[t] = (t < B) ? g_bsum[t] : 0;
    __syncthreads();
    if (t == 0) {
        int run = 0;
        for (int i = 0; i < B; i++) { int x = sm[i]; sm[i] = run; run += x; }
        g_off[N] = E - sm[N >> 10];
    }
    __syncthreads();
    if (t < B) g_boff[t] = sm[t];
}

__global__ void k_scatter(const void* __restrict__ ei, int E) {
    int t = blockIdx.x * blockDim.x + threadIdx.x;
    if (t >= E) return;
    int s, d;
    load_sd(ei, E, t, s, d);
    int pos = atomicAdd(&g_cur[d], 1) + g_boff[d >> 10];
    g_csr[pos] = s;
}

// ---------------- GEMM1 + attention scalars + global max A1 ----------------
__global__ __launch_bounds__(256) void k_gemm1(
    const float* __restrict__ x, const float* __restrict__ W1,
    const float* __restrict__ att_s, const float* __restrict__ att_d, int N)
{
    __shared__ float xt[128][68];
    __shared__ float Ws[128][64];
    __shared__ float sA[2];
    int tid = threadIdx.x;
    int tx = tid & 15, ty = tid >> 4;
    int row0 = blockIdx.x * 64;

    if (tid < 2) sA[tid] = NINF;
    for (int i = tid; i < 128 * 64; i += 256) Ws[i >> 6][i & 63] = W1[i];

    int lr = tid >> 2;
    int kc = (tid & 3) * 32;
    int grow = row0 + lr;
    if (grow < N) {
        const float4* xrow = (const float4*)(x + (size_t)grow * 128);
        #pragma unroll
        for (int i = 0; i < 8; i++) {
            float4 v = xrow[(kc >> 2) + i];
            int k = kc + i * 4;
            xt[k][lr] = v.x; xt[k + 1][lr] = v.y; xt[k + 2][lr] = v.z; xt[k + 3][lr] = v.w;
        }
    } else {
        #pragma unroll
        for (int i = 0; i < 8; i++) {
            int k = kc + i * 4;
            xt[k][lr] = 0.f; xt[k + 1][lr] = 0.f; xt[k + 2][lr] = 0.f; xt[k + 3][lr] = 0.f;
        }
    }
    __syncthreads();

    float acc[4][4];
    #pragma unroll
    for (int i = 0; i < 4; i++)
        #pragma unroll
        for (int j = 0; j < 4; j++) acc[i][j] = 0.f;

    #pragma unroll 4
    for (int k = 0; k < 128; k++) {
        float4 xv = *(const float4*)&xt[k][ty * 4];
        float4 wv = *(const float4*)&Ws[k][tx * 4];
        float xa[4] = {xv.x, xv.y, xv.z, xv.w};
        float wa[4] = {wv.x, wv.y, wv.z, wv.w};
        #pragma unroll
        for (int i = 0; i < 4; i++)
            #pragma unroll
            for (int j = 0; j < 4; j++) acc[i][j] += xa[i] * wa[j];
    }

    float ps[4], pd[4];
    #pragma unroll
    for (int i = 0; i < 4; i++) {
        ps[i] = 0.f; pd[i] = 0.f;
        #pragma unroll
        for (int j = 0; j < 4; j++) {
            int c = tx * 4 + j;
            ps[i] += acc[i][j] * att_s[c];
            pd[i] += acc[i][j] * att_d[c];
        }
    }
    #pragma unroll
    for (int i = 0; i < 4; i++) {
        int r = row0 + ty * 4 + i;
        if (r < N) {
            __half2 h01 = __float22half2_rn(make_float2(acc[i][0], acc[i][1]));
            __half2 h23 = __float22half2_rn(make_float2(acc[i][2], acc[i][3]));
            uint2 u;
            u.x = *(const unsigned int*)&h01;
            u.y = *(const unsigned int*)&h23;
            ((uint2*)g_h1)[(size_t)r * 16 + tx] = u;
        }
    }
    #pragma unroll
    for (int o = 1; o < 8; o <<= 1) {
        #pragma unroll
        for (int i = 0; i < 4; i++) {
            ps[i] += __shfl_xor_sync(0xffffffffu, ps[i], o);
            pd[i] += __shfl_xor_sync(0xffffffffu, pd[i], o);
        }
    }
    if ((tx & 7) == 0) {
        int head = tx >> 3;
        #pragma unroll
        for (int i = 0; i < 4; i++) {
            int r = row0 + ty * 4 + i;
            if (r < N) {
                g_a1s[r * 2 + head] = ps[i];
                g_a1d[r * 2 + head] = pd[i];
                atomicMaxFloat(&sA[head], ps[i]);
            }
        }
    }
    __syncthreads();
    if (tid < 2) atomicMaxFloat(&g_A1[tid], sA[tid]);
}

// ---------------- layer1 aggregate + normalize + relu + GEMM2 + att2 (fused) ----------
// 512 threads = 16 warps per block; weights loaded once per block serve 16 warps
__global__ __launch_bounds__(512) void k_acc1(
    const float* __restrict__ Wmu, const float* __restrict__ Wls,
    const float* __restrict__ b1,
    const float* __restrict__ asmu, const float* __restrict__ admu,
    const float* __restrict__ asls, const float* __restrict__ adls, int N)
{
    __shared__ float Ws[2][1040];
    __shared__ float h2s[16][64];
    __shared__ float att[4][16];
    __shared__ float b1s[64];
    __shared__ float blkmax[2];
    int tid = threadIdx.x;
    for (int i = tid; i < 1024; i += 512) { Ws[0][i] = Wmu[i]; Ws[1][i] = Wls[i]; }
    if (tid < 16) {
        att[0][tid] = asmu[tid]; att[1][tid] = admu[tid];
        att[2][tid] = asls[tid]; att[3][tid] = adls[tid];
    }
    if (tid < 64) b1s[tid] = b1[tid];
    if (tid < 2) blkmax[tid] = NINF;
    __syncthreads();

    int lane = tid & 31, warp = tid >> 5;
    int group = lane >> 4, l = lane & 15, head = l >> 3;
    int sel = lane >> 4, col = lane & 15;
    float A = g_A1[head];
    float localmax = NINF;
    int nwarps = gridDim.x * 16;

    for (int node = blockIdx.x * 16 + warp; node < N; node += nwarps) {
        __syncwarp();
        float adn = g_a1d[node * 2 + head];
        float m = lrelu(A + adn);
        float4 acc = {0.f, 0.f, 0.f, 0.f};
        float den = 0.f;
        if (group == 0) {   // self loop
            float e = lrelu(g_a1s[node * 2 + head] + adn);
            float ex = __expf(e - m);
            float2 f01, f23;
            load_h1_4(node, l, f01, f23);
            acc.x = ex * f01.x; acc.y = ex * f01.y; acc.z = ex * f23.x; acc.w = ex * f23.y;
            den = ex;
        }
        int beg = g_off[node] + g_boff[node >> 10];
        int end = beg + g_deg[node];
        int i = beg + group;
        int sn = (i < end) ? g_csr[i] : 0;
        while (i < end) {
            int s = sn;
            int inext = i + 2;
            if (inext < end) sn = g_csr[inext];
            float e = lrelu(g_a1s[s * 2 + head] + adn);
            float ex = __expf(e - m);
            float2 f01, f23;
            load_h1_4(s, l, f01, f23);
            acc.x += ex * f01.x; acc.y += ex * f01.y; acc.z += ex * f23.x; acc.w += ex * f23.y;
            den += ex;
            i = inext;
        }
        acc.x += __shfl_xor_sync(~0u, acc.x, 16);
        acc.y += __shfl_xor_sync(~0u, acc.y, 16);
        acc.z += __shfl_xor_sync(~0u, acc.z, 16);
        acc.w += __shfl_xor_sync(~0u, acc.w, 16);
        den   += __shfl_xor_sync(~0u, den, 16);
        if (group == 0) {
            float inv = 1.f / (den + 1e-16f);
            float v0 = fmaxf(acc.x * inv + b1s[4 * l + 0], 0.f);
            float v1 = fmaxf(acc.y * inv + b1s[4 * l + 1], 0.f);
            float v2 = fmaxf(acc.z * inv + b1s[4 * l + 2], 0.f);
            float v3 = fmaxf(acc.w * inv + b1s[4 * l + 3], 0.f);
            *(float4*)&h2s[warp][4 * l] = make_float4(v0, v1, v2, v3);
        }
        __syncwarp();
        const float* W = Ws[sel];
        float a = 0.f;
        #pragma unroll
        for (int k = 0; k < 64; k++) a += h2s[warp][k] * W[k * 16 + col];
        g_g2[(size_t)node * 32 + lane] = a;
        float ps = a * att[sel * 2 + 0][col];
        float pd = a * att[sel * 2 + 1][col];
        #pragma unroll
        for (int o = 8; o > 0; o >>= 1) {
            ps += __shfl_xor_sync(~0u, ps, o);
            pd += __shfl_xor_sync(~0u, pd, o);
        }
        if (col == 0) {
            g_a2s[node * 2 + sel] = ps;
            g_a2d[node * 2 + sel] = pd;
            localmax = fmaxf(localmax, ps);
        }
    }
    if (col == 0) atomicMaxFloat(&blkmax[sel], localmax);
    __syncthreads();
    if (tid < 2) atomicMaxFloat(&g_A2[tid], blkmax[tid]);
}

// ---------------- layer2 aggregate + normalize + bias + output (fused) ----------------
__global__ __launch_bounds__(512) void k_acc2(
    const float* __restrict__ bmu, const float* __restrict__ bls,
    float* __restrict__ out, int N)
{
    int tid = threadIdx.x, lane = tid & 31, warp = tid >> 5;
    int group = lane >> 3, l = lane & 7, sel = l >> 2;
    float A = g_A2[sel];
    int nwarps = gridDim.x * 16;
    for (int node = blockIdx.x * 16 + warp; node < N; node += nwarps) {
        float adn = g_a2d[node * 2 + sel];
        float m = lrelu(A + adn);
        float4 acc = {0.f, 0.f, 0.f, 0.f};
        float den = 0.f;
        if (group == 0) {   // self loop
            float e = lrelu(g_a2s[node * 2 + sel] + adn);
            float ex = __expf(e - m);
            float4 g = ((const float4*)g_g2)[(size_t)node * 8 + l];
            acc.x = ex * g.x; acc.y = ex * g.y; acc.z = ex * g.z; acc.w = ex * g.w;
            den = ex;
        }
        int beg = g_off[node] + g_boff[node >> 10];
        int end = beg + g_deg[node];
        int i = beg + group;
        int sn = (i < end) ? g_csr[i] : 0;
        while (i < end) {
            int s = sn;
            int inext = i + 4;
            if (inext < end) sn = g_csr[inext];
            float e = lrelu(g_a2s[s * 2 + sel] + adn);
            float ex = __expf(e - m);
            float4 g = ((const float4*)g_g2)[(size_t)s * 8 + l];
            acc.x += ex * g.x; acc.y += ex * g.y; acc.z += ex * g.z; acc.w += ex * g.w;
            den += ex;
            i = inext;
        }
        #pragma unroll
        for (int o = 8; o <= 16; o <<= 1) {
            acc.x += __shfl_xor_sync(~0u, acc.x, o);
            acc.y += __shfl_xor_sync(~0u, acc.y, o);
            acc.z += __shfl_xor_sync(~0u, acc.z, o);
            acc.w += __shfl_xor_sync(~0u, acc.w, o);
            den   += __shfl_xor_sync(~0u, den, o);
        }
        if (group == 0) {
            float inv = 1.f / (den + 1e-16f);
            float4 v;
            v.x = acc.x * inv; v.y = acc.y * inv; v.z = acc.z * inv; v.w = acc.w * inv;
            if (sel == 0) {
                float4 bv = ((const float4*)bmu)[l];
                v.x += bv.x; v.y += bv.y; v.z += bv.z; v.w += bv.w;
                ((float4*)out)[(size_t)node * 4 + l] = v;
            } else {
                float4 bv = ((const float4*)bls)[l - 4];
                v.x += bv.x; v.y += bv.y; v.z += bv.z; v.w += bv.w;
                ((float4*)(out + (size_t)N * 16))[(size_t)node * 4 + (l - 4)] = v;
            }
        }
    }
}

// ---------------- launch ----------------
extern "C" void kernel_launch(void* const* d_in, const int* in_sizes, int n_in,
                              void* d_out, int out_size) {
    const float* x    = (const float*)d_in[0];
    const void*  ei   = d_in[1];
    const float* W1   = (const float*)d_in[2];
    const float* as1  = (const float*)d_in[3];
    const float* ad1  = (const float*)d_in[4];
    const float* b1   = (const float*)d_in[5];
    const float* Wmu  = (const float*)d_in[6];
    const float* asmu = (const float*)d_in[7];
    const float* admu = (const float*)d_in[8];
    const float* bmu  = (const float*)d_in[9];
    const float* Wls  = (const float*)d_in[10];
    const float* asls = (const float*)d_in[11];
    const float* adls = (const float*)d_in[12];
    const float* bls  = (const float*)d_in[13];
    float* out = (float*)d_out;

    int N = in_sizes[0] / 128;
    int E = in_sizes[1] / 2;
    int B1 = (N + 1023) / 1024;

    k_init<<<(N + 255) / 256, 256>>>((const int*)ei, E, N);
    k_hist<<<(E + 255) / 256, 256>>>(ei, E);
    k_gemm1<<<(N + 63) / 64, 256>>>(x, W1, as1, ad1, N);
    k_scan1<<<B1, 256>>>(N);
    k_scan2<<<1, 64>>>(B1, E, N);
    k_scatter<<<(E + 255) / 256, 256>>>(ei, E);
    k_acc1<<<1184, 512>>>(Wmu, Wls, b1, asmu, admu, asls, adls, N);
    k_acc2<<<1184, 512>>>(bmu, bls, out, N);
}

// round 16
// speedup vs baseline: 1.1116x; 1.0038x over previous
#include <cuda_runtime.h>
#include <cuda_fp16.h>

#define NMAX 50016
#define EMAX 1600000
#define NEG 0.2f
#define NINF __int_as_float(0xff800000)

// ---------------- scratch ----------------
__device__ __align__(256) __half g_h1[NMAX * 64];    // layer1 features (fp16 values)
__device__ __align__(256) float g_g2[NMAX * 32];     // layer2 features (mu|ls), fp32
__device__ float g_a1s[NMAX * 2], g_a1d[NMAX * 2];
__device__ float g_a2s[NMAX * 2], g_a2d[NMAX * 2];
__device__ float g_A1[2], g_A2[2];                   // global maxima of a_src per head
__device__ __align__(16) int g_deg[NMAX];
__device__ int g_off[NMAX + 1];
__device__ int g_bsum[64], g_boff[64];
__device__ int g_csr[EMAX];
__device__ int g_rank[EMAX];
__device__ int g_is64;

// ---------------- helpers ----------------
__device__ __forceinline__ void atomicMaxFloat(float* addr, float v) {
    if (v >= 0.f) atomicMax((int*)addr, __float_as_int(v));
    else          atomicMin((unsigned int*)addr, __float_as_uint(v));
}
__device__ __forceinline__ float lrelu(float v) { return v > 0.f ? v : NEG * v; }

__device__ __forceinline__ void load_sd(const void* ei, int E, int t, int& s, int& d) {
    if (g_is64) {
        const long long* p = (const long long*)ei;
        s = (int)p[t]; d = (int)p[(long long)E + t];
    } else {
        const int* p = (const int*)ei;
        s = p[t]; d = p[E + t];
    }
}

// load 4 fp16 h1 values (cols 4l..4l+3 of node row) as 2 float2
__device__ __forceinline__ void load_h1_4(int node, int l, float2& f01, float2& f23) {
    uint2 u = ((const uint2*)g_h1)[(size_t)node * 16 + l];
    f01 = __half22float2(*(const __half2*)&u.x);
    f23 = __half22float2(*(const __half2*)&u.y);
}

// ---------------- init + dtype detect ----------------
__global__ void k_init(const int* ei32, int E, int N) {
    int i = blockIdx.x * blockDim.x + threadIdx.x;
    if (i < N) g_deg[i] = 0;
    if (i < 2) { g_A1[i] = NINF; g_A2[i] = NINF; }
    if (blockIdx.x == 0) {
        __shared__ int any;
        if (threadIdx.x == 0) any = 0;
        __syncthreads();
        int n = min(2 * E, 4096);
        for (int j = threadIdx.x; 2 * j + 1 < n; j += blockDim.x)
            if (ei32[2 * j + 1] != 0) any = 1;
        __syncthreads();
        if (threadIdx.x == 0) g_is64 = (any == 0) ? 1 : 0;
    }
}

// ---------------- CSR build: histogram that ALSO records each edge's bucket rank ----
__global__ void k_hist(const void* __restrict__ ei, int E) {
    int t = blockIdx.x * blockDim.x + threadIdx.x;
    if (t >= E) return;
    int d;
    if (g_is64) d = (int)((const long long*)ei)[(long long)E + t];
    else        d = ((const int*)ei)[E + t];
    g_rank[t] = atomicAdd(&g_deg[d], 1);
}

// block-local exclusive scan; writes local offsets to g_off
__global__ void k_scan1(int N) {
    int t = threadIdx.x, b = blockIdx.x;
    int base = b * 1024 + t * 4;
    int v0 = 0, v1 = 0, v2 = 0, v3 = 0;
    if (base + 3 < N) {
        int4 q = *(const int4*)&g_deg[base];
        v0 = q.x; v1 = q.y; v2 = q.z; v3 = q.w;
    } else {
        if (base < N)     v0 = g_deg[base];
        if (base + 1 < N) v1 = g_deg[base + 1];
        if (base + 2 < N) v2 = g_deg[base + 2];
        if (base + 3 < N) v3 = g_deg[base + 3];
    }
    int s = v0 + v1 + v2 + v3;
    int lane = t & 31, warp = t >> 5;
    int incl = s;
    #pragma unroll
    for (int o = 1; o < 32; o <<= 1) {
        int nv = __shfl_up_sync(~0u, incl, o);
        if (lane >= o) incl += nv;
    }
    __shared__ int wsum[8];
    if (lane == 31) wsum[warp] = incl;
    __syncthreads();
    if (t == 0) {
        int run = 0;
        #pragma unroll
        for (int w = 0; w < 8; w++) { int x = wsum[w]; wsum[w] = run; run += x; }
        g_bsum[b] = run;
    }
    __syncthreads();
    int excl = incl - s + wsum[warp];
    if (base < N)     g_off[base]     = excl;
    if (base + 1 < N) g_off[base + 1] = excl + v0;
    if (base + 2 < N) g_off[base + 2] = excl + v0 + v1;
    if (base + 3 < N) g_off[base + 3] = excl + v0 + v1 + v2;
}

// block-base exclusive scan
__global__ void k_scan2(int B, int E, int N) {
    __shared__ int sm[64];
    int t = threadIdx.x;
    sm[t] = (t < B) ? g_bsum[t] : 0;
    __syncthreads();
    if (t == 0) {
        int run = 0;
        for (int i = 0; i < B; i++) { int x = sm[i]; sm[i] = run; run += x; }
        g_off[N] = E - sm[N >> 10];
    }
    __syncthreads();
    if (t < B) g_boff[t] = sm[t];
}

// atomic-free scatter: rank recorded during hist
__global__ void k_scatter(const void* __restrict__ ei, int E) {
    int t = blockIdx.x * blockDim.x + threadIdx.x;
    if (t >= E) return;
    int s, d;
    load_sd(ei, E, t, s, d);
    int pos = g_off[d] + g_boff[d >> 10] + g_rank[t];
    g_csr[pos] = s;
}

// ---------------- GEMM1 + attention scalars + global max A1 ----------------
__global__ __launch_bounds__(256) void k_gemm1(
    const float* __restrict__ x, const float* __restrict__ W1,
    const float* __restrict__ att_s, const float* __restrict__ att_d, int N)
{
    __shared__ float xt[128][68];
    __shared__ float Ws[128][64];
    __shared__ float sA[2];
    int tid = threadIdx.x;
    int tx = tid & 15, ty = tid >> 4;
    int row0 = blockIdx.x * 64;

    if (tid < 2) sA[tid] = NINF;
    for (int i = tid; i < 128 * 64; i += 256) Ws[i >> 6][i & 63] = W1[i];

    int lr = tid >> 2;
    int kc = (tid & 3) * 32;
    int grow = row0 + lr;
    if (grow < N) {
        const float4* xrow = (const float4*)(x + (size_t)grow * 128);
        #pragma unroll
        for (int i = 0; i < 8; i++) {
            float4 v = xrow[(kc >> 2) + i];
            int k = kc + i * 4;
            xt[k][lr] = v.x; xt[k + 1][lr] = v.y; xt[k + 2][lr] = v.z; xt[k + 3][lr] = v.w;
        }
    } else {
        #pragma unroll
        for (int i = 0; i < 8; i++) {
            int k = kc + i * 4;
            xt[k][lr] = 0.f; xt[k + 1][lr] = 0.f; xt[k + 2][lr] = 0.f; xt[k + 3][lr] = 0.f;
        }
    }
    __syncthreads();

    float acc[4][4];
    #pragma unroll
    for (int i = 0; i < 4; i++)
        #pragma unroll
        for (int j = 0; j < 4; j++) acc[i][j] = 0.f;

    #pragma unroll 4
    for (int k = 0; k < 128; k++) {
        float4 xv = *(const float4*)&xt[k][ty * 4];
        float4 wv = *(const float4*)&Ws[k][tx * 4];
        float xa[4] = {xv.x, xv.y, xv.z, xv.w};
        float wa[4] = {wv.x, wv.y, wv.z, wv.w};
        #pragma unroll
        for (int i = 0; i < 4; i++)
            #pragma unroll
            for (int j = 0; j < 4; j++) acc[i][j] += xa[i] * wa[j];
    }

    float ps[4], pd[4];
    #pragma unroll
    for (int i = 0; i < 4; i++) {
        ps[i] = 0.f; pd[i] = 0.f;
        #pragma unroll
        for (int j = 0; j < 4; j++) {
            int c = tx * 4 + j;
            ps[i] += acc[i][j] * att_s[c];
            pd[i] += acc[i][j] * att_d[c];
        }
    }
    #pragma unroll
    for (int i = 0; i < 4; i++) {
        int r = row0 + ty * 4 + i;
        if (r < N) {
            __half2 h01 = __float22half2_rn(make_float2(acc[i][0], acc[i][1]));
            __half2 h23 = __float22half2_rn(make_float2(acc[i][2], acc[i][3]));
            uint2 u;
            u.x = *(const unsigned int*)&h01;
            u.y = *(const unsigned int*)&h23;
            ((uint2*)g_h1)[(size_t)r * 16 + tx] = u;
        }
    }
    #pragma unroll
    for (int o = 1; o < 8; o <<= 1) {
        #pragma unroll
        for (int i = 0; i < 4; i++) {
            ps[i] += __shfl_xor_sync(0xffffffffu, ps[i], o);
            pd[i] += __shfl_xor_sync(0xffffffffu, pd[i], o);
        }
    }
    if ((tx & 7) == 0) {
        int head = tx >> 3;
        #pragma unroll
        for (int i = 0; i < 4; i++) {
            int r = row0 + ty * 4 + i;
            if (r < N) {
                g_a1s[r * 2 + head] = ps[i];
                g_a1d[r * 2 + head] = pd[i];
                atomicMaxFloat(&sA[head], ps[i]);
            }
        }
    }
    __syncthreads();
    if (tid < 2) atomicMaxFloat(&g_A1[tid], sA[tid]);
}

// ---------------- layer1 aggregate + normalize + relu + GEMM2 + att2 (fused) ----------
__global__ __launch_bounds__(512) void k_acc1(
    const float* __restrict__ Wmu, const float* __restrict__ Wls,
    const float* __restrict__ b1,
    const float* __restrict__ asmu, const float* __restrict__ admu,
    const float* __restrict__ asls, const float* __restrict__ adls, int N)
{
    __shared__ float Ws[2][1040];
    __shared__ float h2s[16][64];
    __shared__ float att[4][16];
    __shared__ float b1s[64];
    __shared__ float blkmax[2];
    int tid = threadIdx.x;
    for (int i = tid; i < 1024; i += 512) { Ws[0][i] = Wmu[i]; Ws[1][i] = Wls[i]; }
    if (tid < 16) {
        att[0][tid] = asmu[tid]; att[1][tid] = admu[tid];
        att[2][tid] = asls[tid]; att[3][tid] = adls[tid];
    }
    if (tid < 64) b1s[tid] = b1[tid];
    if (tid < 2) blkmax[tid] = NINF;
    __syncthreads();

    int lane = tid & 31, warp = tid >> 5;
    int group = lane >> 4, l = lane & 15, head = l >> 3;
    int sel = lane >> 4, col = lane & 15;
    float A = g_A1[head];
    float localmax = NINF;
    int nwarps = gridDim.x * 16;

    for (int node = blockIdx.x * 16 + warp; node < N; node += nwarps) {
        __syncwarp();
        float adn = g_a1d[node * 2 + head];
        float m = lrelu(A + adn);
        float4 acc = {0.f, 0.f, 0.f, 0.f};
        float den = 0.f;
        if (group == 0) {   // self loop
            float e = lrelu(g_a1s[node * 2 + head] + adn);
            float ex = __expf(e - m);
            float2 f01, f23;
            load_h1_4(node, l, f01, f23);
            acc.x = ex * f01.x; acc.y = ex * f01.y; acc.z = ex * f23.x; acc.w = ex * f23.y;
            den = ex;
        }
        int beg = g_off[node] + g_boff[node >> 10];
        int end = beg + g_deg[node];
        int i = beg + group;
        int sn = (i < end) ? g_csr[i] : 0;
        while (i < end) {
            int s = sn;
            int inext = i + 2;
            if (inext < end) sn = g_csr[inext];
            float e = lrelu(g_a1s[s * 2 + head] + adn);
            float ex = __expf(e - m);
            float2 f01, f23;
            load_h1_4(s, l, f01, f23);
            acc.x += ex * f01.x; acc.y += ex * f01.y; acc.z += ex * f23.x; acc.w += ex * f23.y;
            den += ex;
            i = inext;
        }
        acc.x += __shfl_xor_sync(~0u, acc.x, 16);
        acc.y += __shfl_xor_sync(~0u, acc.y, 16);
        acc.z += __shfl_xor_sync(~0u, acc.z, 16);
        acc.w += __shfl_xor_sync(~0u, acc.w, 16);
        den   += __shfl_xor_sync(~0u, den, 16);
        if (group == 0) {
            float inv = 1.f / (den + 1e-16f);
            float v0 = fmaxf(acc.x * inv + b1s[4 * l + 0], 0.f);
            float v1 = fmaxf(acc.y * inv + b1s[4 * l + 1], 0.f);
            float v2 = fmaxf(acc.z * inv + b1s[4 * l + 2], 0.f);
            float v3 = fmaxf(acc.w * inv + b1s[4 * l + 3], 0.f);
            *(float4*)&h2s[warp][4 * l] = make_float4(v0, v1, v2, v3);
        }
        __syncwarp();
        const float* W = Ws[sel];
        float a = 0.f;
        #pragma unroll
        for (int k = 0; k < 64; k++) a += h2s[warp][k] * W[k * 16 + col];
        g_g2[(size_t)node * 32 + lane] = a;
        float ps = a * att[sel * 2 + 0][col];
        float pd = a * att[sel * 2 + 1][col];
        #pragma unroll
        for (int o = 8; o > 0; o >>= 1) {
            ps += __shfl_xor_sync(~0u, ps, o);
            pd += __shfl_xor_sync(~0u, pd, o);
        }
        if (col == 0) {
            g_a2s[node * 2 + sel] = ps;
            g_a2d[node * 2 + sel] = pd;
            localmax = fmaxf(localmax, ps);
        }
    }
    if (col == 0) atomicMaxFloat(&blkmax[sel], localmax);
    __syncthreads();
    if (tid < 2) atomicMaxFloat(&g_A2[tid], blkmax[tid]);
}

// ---------------- layer2 aggregate + normalize + bias + output (fused) ----------------
__global__ __launch_bounds__(512) void k_acc2(
    const float* __restrict__ bmu, const float* __restrict__ bls,
    float* __restrict__ out, int N)
{
    int tid = threadIdx.x, lane = tid & 31, warp = tid >> 5;
    int group = lane >> 3, l = lane & 7, sel = l >> 2;
    float A = g_A2[sel];
    int nwarps = gridDim.x * 16;
    for (int node = blockIdx.x * 16 + warp; node < N; node += nwarps) {
        float adn = g_a2d[node * 2 + sel];
        float m = lrelu(A + adn);
        float4 acc = {0.f, 0.f, 0.f, 0.f};
        float den = 0.f;
        if (group == 0) {   // self loop
            float e = lrelu(g_a2s[node * 2 + sel] + adn);
            float ex = __expf(e - m);
            float4 g = ((const float4*)g_g2)[(size_t)node * 8 + l];
            acc.x = ex * g.x; acc.y = ex * g.y; acc.z = ex * g.z; acc.w = ex * g.w;
            den = ex;
        }
        int beg = g_off[node] + g_boff[node >> 10];
        int end = beg + g_deg[node];
        int i = beg + group;
        int sn = (i < end) ? g_csr[i] : 0;
        while (i < end) {
            int s = sn;
            int inext = i + 4;
            if (inext < end) sn = g_csr[inext];
            float e = lrelu(g_a2s[s * 2 + sel] + adn);
            float ex = __expf(e - m);
            float4 g = ((const float4*)g_g2)[(size_t)s * 8 + l];
            acc.x += ex * g.x; acc.y += ex * g.y; acc.z += ex * g.z; acc.w += ex * g.w;
            den += ex;
            i = inext;
        }
        #pragma unroll
        for (int o = 8; o <= 16; o <<= 1) {
            acc.x += __shfl_xor_sync(~0u, acc.x, o);
            acc.y += __shfl_xor_sync(~0u, acc.y, o);
            acc.z += __shfl_xor_sync(~0u, acc.z, o);
            acc.w += __shfl_xor_sync(~0u, acc.w, o);
            den   += __shfl_xor_sync(~0u, den, o);
        }
        if (group == 0) {
            float inv = 1.f / (den + 1e-16f);
            float4 v;
            v.x = acc.x * inv; v.y = acc.y * inv; v.z = acc.z * inv; v.w = acc.w * inv;
            if (sel == 0) {
                float4 bv = ((const float4*)bmu)[l];
                v.x += bv.x; v.y += bv.y; v.z += bv.z; v.w += bv.w;
                ((float4*)out)[(size_t)node * 4 + l] = v;
            } else {
                float4 bv = ((const float4*)bls)[l - 4];
                v.x += bv.x; v.y += bv.y; v.z += bv.z; v.w += bv.w;
                ((float4*)(out + (size_t)N * 16))[(size_t)node * 4 + (l - 4)] = v;
            }
        }
    }
}

// ---------------- launch ----------------
extern "C" void kernel_launch(void* const* d_in, const int* in_sizes, int n_in,
                              void* d_out, int out_size) {
    const float* x    = (const float*)d_in[0];
    const void*  ei   = d_in[1];
    const float* W1   = (const float*)d_in[2];
    const float* as1  = (const float*)d_in[3];
    const float* ad1  = (const float*)d_in[4];
    const float* b1   = (const float*)d_in[5];
    const float* Wmu  = (const float*)d_in[6];
    const float* asmu = (const float*)d_in[7];
    const float* admu = (const float*)d_in[8];
    const float* bmu  = (const float*)d_in[9];
    const float* Wls  = (const float*)d_in[10];
    const float* asls = (const float*)d_in[11];
    const float* adls = (const float*)d_in[12];
    const float* bls  = (const float*)d_in[13];
    float* out = (float*)d_out;

    int N = in_sizes[0] / 128;
    int E = in_sizes[1] / 2;
    int B1 = (N + 1023) / 1024;

    k_init<<<(N + 255) / 256, 256>>>((const int*)ei, E, N);
    k_hist<<<(E + 255) / 256, 256>>>(ei, E);
    k_gemm1<<<(N + 63) / 64, 256>>>(x, W1, as1, ad1, N);
    k_scan1<<<B1, 256>>>(N);
    k_scan2<<<1, 64>>>(B1, E, N);
    k_scatter<<<(E + 255) / 256, 256>>>(ei, E);
    k_acc1<<<1184, 512>>>(Wmu, Wls, b1, asmu, admu, asls, adls, N);
    k_acc2<<<1184, 512>>>(bmu, bls, out, N);
}

// round 17
// speedup vs baseline: 1.1383x; 1.0240x over previous
#include <cuda_runtime.h>
#include <cuda_fp16.h>

#define NMAX 50016
#define EMAX 1600000
#define NEG 0.2f
#define NINF __int_as_float(0xff800000)

// ---------------- scratch ----------------
__device__ __align__(256) __half g_h1[NMAX * 64];    // layer1 features (fp16 values)
__device__ __align__(256) float g_g2[NMAX * 32];     // layer2 features (mu|ls), fp32
__device__ float g_a1s[NMAX * 2], g_a1d[NMAX * 2];
__device__ float g_a2s[NMAX * 2], g_a2d[NMAX * 2];
__device__ float g_A1[2], g_A2[2];                   // global maxima of a_src per head
__device__ __align__(16) int g_deg[NMAX];
__device__ int g_off[NMAX + 1];
__device__ int g_bsum[64], g_boff[64];
__device__ int g_csr[EMAX];
__device__ int g_rank[EMAX];
__device__ int g_is64;

// ---------------- helpers ----------------
__device__ __forceinline__ void atomicMaxFloat(float* addr, float v) {
    if (v >= 0.f) atomicMax((int*)addr, __float_as_int(v));
    else          atomicMin((unsigned int*)addr, __float_as_uint(v));
}
__device__ __forceinline__ float lrelu(float v) { return v > 0.f ? v : NEG * v; }

// packed fp32x2 FMA (FFMA2) — only reachable via PTX; bit-identical to 2x FFMA
#define PACKF2(out, lo, hi) \
    asm("mov.b64 %0, {%1, %2};" : "=l"(out) : "f"(lo), "f"(hi))
#define UNPACKF2(lo, hi, in) \
    asm("mov.b64 {%0, %1}, %2;" : "=f"(lo), "=f"(hi) : "l"(in))
#define FMAF2(acc, a, b) \
    asm("fma.rn.f32x2 %0, %1, %2, %3;" : "=l"(acc) : "l"(a), "l"(b), "l"(acc))

__device__ __forceinline__ void load_sd(const void* ei, int E, int t, int& s, int& d) {
    if (g_is64) {
        const long long* p = (const long long*)ei;
        s = (int)p[t]; d = (int)p[(long long)E + t];
    } else {
        const int* p = (const int*)ei;
        s = p[t]; d = p[E + t];
    }
}

// load 4 fp16 h1 values (cols 4l..4l+3 of node row) as 2 float2
__device__ __forceinline__ void load_h1_4(int node, int l, float2& f01, float2& f23) {
    uint2 u = ((const uint2*)g_h1)[(size_t)node * 16 + l];
    f01 = __half22float2(*(const __half2*)&u.x);
    f23 = __half22float2(*(const __half2*)&u.y);
}

// ---------------- init + dtype detect ----------------
__global__ void k_init(const int* ei32, int E, int N) {
    int i = blockIdx.x * blockDim.x + threadIdx.x;
    if (i < N) g_deg[i] = 0;
    if (i < 2) { g_A1[i] = NINF; g_A2[i] = NINF; }
    if (blockIdx.x == 0) {
        __shared__ int any;
        if (threadIdx.x == 0) any = 0;
        __syncthreads();
        int n = min(2 * E, 4096);
        for (int j = threadIdx.x; 2 * j + 1 < n; j += blockDim.x)
            if (ei32[2 * j + 1] != 0) any = 1;
        __syncthreads();
        if (threadIdx.x == 0) g_is64 = (any == 0) ? 1 : 0;
    }
}

// ---------------- CSR build: histogram that ALSO records each edge's bucket rank ----
__global__ void k_hist(const void* __restrict__ ei, int E) {
    int t = blockIdx.x * blockDim.x + threadIdx.x;
    if (t >= E) return;
    int d;
    if (g_is64) d = (int)((const long long*)ei)[(long long)E + t];
    else        d = ((const int*)ei)[E + t];
    g_rank[t] = atomicAdd(&g_deg[d], 1);
}

// block-local exclusive scan; writes local offsets to g_off
__global__ void k_scan1(int N) {
    int t = threadIdx.x, b = blockIdx.x;
    int base = b * 1024 + t * 4;
    int v0 = 0, v1 = 0, v2 = 0, v3 = 0;
    if (base + 3 < N) {
        int4 q = *(const int4*)&g_deg[base];
        v0 = q.x; v1 = q.y; v2 = q.z; v3 = q.w;
    } else {
        if (base < N)     v0 = g_deg[base];
        if (base + 1 < N) v1 = g_deg[base + 1];
        if (base + 2 < N) v2 = g_deg[base + 2];
        if (base + 3 < N) v3 = g_deg[base + 3];
    }
    int s = v0 + v1 + v2 + v3;
    int lane = t & 31, warp = t >> 5;
    int incl = s;
    #pragma unroll
    for (int o = 1; o < 32; o <<= 1) {
        int nv = __shfl_up_sync(~0u, incl, o);
        if (lane >= o) incl += nv;
    }
    __shared__ int wsum[8];
    if (lane == 31) wsum[warp] = incl;
    __syncthreads();
    if (t == 0) {
        int run = 0;
        #pragma unroll
        for (int w = 0; w < 8; w++) { int x = wsum[w]; wsum[w] = run; run += x; }
        g_bsum[b] = run;
    }
    __syncthreads();
    int excl = incl - s + wsum[warp];
    if (base < N)     g_off[base]     = excl;
    if (base + 1 < N) g_off[base + 1] = excl + v0;
    if (base + 2 < N) g_off[base + 2] = excl + v0 + v1;
    if (base + 3 < N) g_off[base + 3] = excl + v0 + v1 + v2;
}

// block-base exclusive scan
__global__ void k_scan2(int B, int E, int N) {
    __shared__ int sm[64];
    int t = threadIdx.x;
    sm[t] = (t < B) ? g_bsum[t] : 0;
    __syncthreads();
    if (t == 0) {
        int run = 0;
        for (int i = 0; i < B; i++) { int x = sm[i]; sm[i] = run; run += x; }
        g_off[N] = E - sm[N >> 10];
    }
    __syncthreads();
    if (t < B) g_boff[t] = sm[t];
}

// atomic-free scatter: rank recorded during hist
__global__ void k_scatter(const void* __restrict__ ei, int E) {
    int t = blockIdx.x * blockDim.x + threadIdx.x;
    if (t >= E) return;
    int s, d;
    load_sd(ei, E, t, s, d);
    int pos = g_off[d] + g_boff[d >> 10] + g_rank[t];
    g_csr[pos] = s;
}

// ---------------- GEMM1 (FFMA2 mainloop) + attention scalars + global max A1 --------
__global__ __launch_bounds__(256) void k_gemm1(
    const float* __restrict__ x, const float* __restrict__ W1,
    const float* __restrict__ att_s, const float* __restrict__ att_d, int N)
{
    __shared__ float xt[128][68];
    __shared__ float Ws[128][64];
    __shared__ float sA[2];
    int tid = threadIdx.x;
    int tx = tid & 15, ty = tid >> 4;
    int row0 = blockIdx.x * 64;

    if (tid < 2) sA[tid] = NINF;
    for (int i = tid; i < 128 * 64; i += 256) Ws[i >> 6][i & 63] = W1[i];

    int lr = tid >> 2;
    int kc = (tid & 3) * 32;
    int grow = row0 + lr;
    if (grow < N) {
        const float4* xrow = (const float4*)(x + (size_t)grow * 128);
        #pragma unroll
        for (int i = 0; i < 8; i++) {
            float4 v = xrow[(kc >> 2) + i];
            int k = kc + i * 4;
            xt[k][lr] = v.x; xt[k + 1][lr] = v.y; xt[k + 2][lr] = v.z; xt[k + 3][lr] = v.w;
        }
    } else {
        #pragma unroll
        for (int i = 0; i < 8; i++) {
            int k = kc + i * 4;
            xt[k][lr] = 0.f; xt[k + 1][lr] = 0.f; xt[k + 2][lr] = 0.f; xt[k + 3][lr] = 0.f;
        }
    }
    __syncthreads();

    // packed accumulators: acc01[i] = (acc[i][0], acc[i][1]), acc23[i] = (acc[i][2], acc[i][3])
    unsigned long long acc01[4], acc23[4];
    #pragma unroll
    for (int i = 0; i < 4; i++) { acc01[i] = 0ull; acc23[i] = 0ull; }

    #pragma unroll 4
    for (int k = 0; k < 128; k++) {
        float4 xv = *(const float4*)&xt[k][ty * 4];
        float4 wv = *(const float4*)&Ws[k][tx * 4];
        unsigned long long wa01, wa23;
        PACKF2(wa01, wv.x, wv.y);
        PACKF2(wa23, wv.z, wv.w);
        float xa[4] = {xv.x, xv.y, xv.z, xv.w};
        #pragma unroll
        for (int i = 0; i < 4; i++) {
            unsigned long long xp;
            PACKF2(xp, xa[i], xa[i]);
            FMAF2(acc01[i], xp, wa01);
            FMAF2(acc23[i], xp, wa23);
        }
    }

    float acc[4][4];
    #pragma unroll
    for (int i = 0; i < 4; i++) {
        UNPACKF2(acc[i][0], acc[i][1], acc01[i]);
        UNPACKF2(acc[i][2], acc[i][3], acc23[i]);
    }

    float ps[4], pd[4];
    #pragma unroll
    for (int i = 0; i < 4; i++) {
        ps[i] = 0.f; pd[i] = 0.f;
        #pragma unroll
        for (int j = 0; j < 4; j++) {
            int c = tx * 4 + j;
            ps[i] += acc[i][j] * att_s[c];
            pd[i] += acc[i][j] * att_d[c];
        }
    }
    #pragma unroll
    for (int i = 0; i < 4; i++) {
        int r = row0 + ty * 4 + i;
        if (r < N) {
            __half2 h01 = __float22half2_rn(make_float2(acc[i][0], acc[i][1]));
            __half2 h23 = __float22half2_rn(make_float2(acc[i][2], acc[i][3]));
            uint2 u;
            u.x = *(const unsigned int*)&h01;
            u.y = *(const unsigned int*)&h23;
            ((uint2*)g_h1)[(size_t)r * 16 + tx] = u;
        }
    }
    #pragma unroll
    for (int o = 1; o < 8; o <<= 1) {
        #pragma unroll
        for (int i = 0; i < 4; i++) {
            ps[i] += __shfl_xor_sync(0xffffffffu, ps[i], o);
            pd[i] += __shfl_xor_sync(0xffffffffu, pd[i], o);
        }
    }
    if ((tx & 7) == 0) {
        int head = tx >> 3;
        #pragma unroll
        for (int i = 0; i < 4; i++) {
            int r = row0 + ty * 4 + i;
            if (r < N) {
                g_a1s[r * 2 + head] = ps[i];
                g_a1d[r * 2 + head] = pd[i];
                atomicMaxFloat(&sA[head], ps[i]);
            }
        }
    }
    __syncthreads();
    if (tid < 2) atomicMaxFloat(&g_A1[tid], sA[tid]);
}

// ---------------- layer1 aggregate + normalize + relu + GEMM2 + att2 (fused) ----------
__global__ __launch_bounds__(512) void k_acc1(
    const float* __restrict__ Wmu, const float* __restrict__ Wls,
    const float* __restrict__ b1,
    const float* __restrict__ asmu, const float* __restrict__ admu,
    const float* __restrict__ asls, const float* __restrict__ adls, int N)
{
    __shared__ float Ws[2][1040];
    __shared__ float h2s[16][64];
    __shared__ float att[4][16];
    __shared__ float b1s[64];
    __shared__ float blkmax[2];
    int tid = threadIdx.x;
    for (int i = tid; i < 1024; i += 512) { Ws[0][i] = Wmu[i]; Ws[1][i] = Wls[i]; }
    if (tid < 16) {
        att[0][tid] = asmu[tid]; att[1][tid] = admu[tid];
        att[2][tid] = asls[tid]; att[3][tid] = adls[tid];
    }
    if (tid < 64) b1s[tid] = b1[tid];
    if (tid < 2) blkmax[tid] = NINF;
    __syncthreads();

    int lane = tid & 31, warp = tid >> 5;
    int group = lane >> 4, l = lane & 15, head = l >> 3;
    int sel = lane >> 4, col = lane & 15;
    float A = g_A1[head];
    float localmax = NINF;
    int nwarps = gridDim.x * 16;

    for (int node = blockIdx.x * 16 + warp; node < N; node += nwarps) {
        __syncwarp();
        float adn = g_a1d[node * 2 + head];
        float m = lrelu(A + adn);
        float4 acc = {0.f, 0.f, 0.f, 0.f};
        float den = 0.f;
        if (group == 0) {   // self loop
            float e = lrelu(g_a1s[node * 2 + head] + adn);
            float ex = __expf(e - m);
            float2 f01, f23;
            load_h1_4(node, l, f01, f23);
            acc.x = ex * f01.x; acc.y = ex * f01.y; acc.z = ex * f23.x; acc.w = ex * f23.y;
            den = ex;
        }
        int beg = g_off[node] + g_boff[node >> 10];
        int end = beg + g_deg[node];
        int i = beg + group;
        int sn = (i < end) ? g_csr[i] : 0;
        while (i < end) {
            int s = sn;
            int inext = i + 2;
            if (inext < end) sn = g_csr[inext];
            float e = lrelu(g_a1s[s * 2 + head] + adn);
            float ex = __expf(e - m);
            float2 f01, f23;
            load_h1_4(s, l, f01, f23);
            acc.x += ex * f01.x; acc.y += ex * f01.y; acc.z += ex * f23.x; acc.w += ex * f23.y;
            den += ex;
            i = inext;
        }
        acc.x += __shfl_xor_sync(~0u, acc.x, 16);
        acc.y += __shfl_xor_sync(~0u, acc.y, 16);
        acc.z += __shfl_xor_sync(~0u, acc.z, 16);
        acc.w += __shfl_xor_sync(~0u, acc.w, 16);
        den   += __shfl_xor_sync(~0u, den, 16);
        if (group == 0) {
            float inv = 1.f / (den + 1e-16f);
            float v0 = fmaxf(acc.x * inv + b1s[4 * l + 0], 0.f);
            float v1 = fmaxf(acc.y * inv + b1s[4 * l + 1], 0.f);
            float v2 = fmaxf(acc.z * inv + b1s[4 * l + 2], 0.f);
            float v3 = fmaxf(acc.w * inv + b1s[4 * l + 3], 0.f);
            *(float4*)&h2s[warp][4 * l] = make_float4(v0, v1, v2, v3);
        }
        __syncwarp();
        const float* W = Ws[sel];
        float a = 0.f;
        #pragma unroll
        for (int k = 0; k < 64; k++) a += h2s[warp][k] * W[k * 16 + col];
        g_g2[(size_t)node * 32 + lane] = a;
        float ps = a * att[sel * 2 + 0][col];
        float pd = a * att[sel * 2 + 1][col];
        #pragma unroll
        for (int o = 8; o > 0; o >>= 1) {
            ps += __shfl_xor_sync(~0u, ps, o);
            pd += __shfl_xor_sync(~0u, pd, o);
        }
        if (col == 0) {
            g_a2s[node * 2 + sel] = ps;
            g_a2d[node * 2 + sel] = pd;
            localmax = fmaxf(localmax, ps);
        }
    }
    if (col == 0) atomicMaxFloat(&blkmax[sel], localmax);
    __syncthreads();
    if (tid < 2) atomicMaxFloat(&g_A2[tid], blkmax[tid]);
}

// ---------------- layer2 aggregate + normalize + bias + output (fused) ----------------
__global__ __launch_bounds__(512) void k_acc2(
    const float* __restrict__ bmu, const float* __restrict__ bls,
    float* __restrict__ out, int N)
{
    int tid = threadIdx.x, lane = tid & 31, warp = tid >> 5;
    int group = lane >> 3, l = lane & 7, sel = l >> 2;
    float A = g_A2[sel];
    int nwarps = gridDim.x * 16;
    for (int node = blockIdx.x * 16 + warp; node < N; node += nwarps) {
        float adn = g_a2d[node * 2 + sel];
        float m = lrelu(A + adn);
        float4 acc = {0.f, 0.f, 0.f, 0.f};
        float den = 0.f;
        if (group == 0) {   // self loop
            float e = lrelu(g_a2s[node * 2 + sel] + adn);
            float ex = __expf(e - m);
            float4 g = ((const float4*)g_g2)[(size_t)node * 8 + l];
            acc.x = ex * g.x; acc.y = ex * g.y; acc.z = ex * g.z; acc.w = ex * g.w;
            den = ex;
        }
        int beg = g_off[node] + g_boff[node >> 10];
        int end = beg + g_deg[node];
        int i = beg + group;
        int sn = (i < end) ? g_csr[i] : 0;
        while (i < end) {
            int s = sn;
            int inext = i + 4;
            if (inext < end) sn = g_csr[inext];
            float e = lrelu(g_a2s[s * 2 + sel] + adn);
            float ex = __expf(e - m);
            float4 g = ((const float4*)g_g2)[(size_t)s * 8 + l];
            acc.x += ex * g.x; acc.y += ex * g.y; acc.z += ex * g.z; acc.w += ex * g.w;
            den += ex;
            i = inext;
        }
        #pragma unroll
        for (int o = 8; o <= 16; o <<= 1) {
            acc.x += __shfl_xor_sync(~0u, acc.x, o);
            acc.y += __shfl_xor_sync(~0u, acc.y, o);
            acc.z += __shfl_xor_sync(~0u, acc.z, o);
            acc.w += __shfl_xor_sync(~0u, acc.w, o);
            den   += __shfl_xor_sync(~0u, den, o);
        }
        if (group == 0) {
            float inv = 1.f / (den + 1e-16f);
            float4 v;
            v.x = acc.x * inv; v.y = acc.y * inv; v.z = acc.z * inv; v.w = acc.w * inv;
            if (sel == 0) {
                float4 bv = ((const float4*)bmu)[l];
                v.x += bv.x; v.y += bv.y; v.z += bv.z; v.w += bv.w;
                ((float4*)out)[(size_t)node * 4 + l] = v;
            } else {
                float4 bv = ((const float4*)bls)[l - 4];
                v.x += bv.x; v.y += bv.y; v.z += bv.z; v.w += bv.w;
                ((float4*)(out + (size_t)N * 16))[(size_t)node * 4 + (l - 4)] = v;
            }
        }
    }
}

// ---------------- launch ----------------
extern "C" void kernel_launch(void* const* d_in, const int* in_sizes, int n_in,
                              void* d_out, int out_size) {
    const float* x    = (const float*)d_in[0];
    const void*  ei   = d_in[1];
    const float* W1   = (const float*)d_in[2];
    const float* as1  = (const float*)d_in[3];
    const float* ad1  = (const float*)d_in[4];
    const float* b1   = (const float*)d_in[5];
    const float* Wmu  = (const float*)d_in[6];
    const float* asmu = (const float*)d_in[7];
    const float* admu = (const float*)d_in[8];
    const float* bmu  = (const float*)d_in[9];
    const float* Wls  = (const float*)d_in[10];
    const float* asls = (const float*)d_in[11];
    const float* adls = (const float*)d_in[12];
    const float* bls  = (const float*)d_in[13];
    float* out = (float*)d_out;

    int N = in_sizes[0] / 128;
    int E = in_sizes[1] / 2;
    int B1 = (N + 1023) / 1024;

    k_init<<<(N + 255) / 256, 256>>>((const int*)ei, E, N);
    k_hist<<<(E + 255) / 256, 256>>>(ei, E);
    k_gemm1<<<(N + 63) / 64, 256>>>(x, W1, as1, ad1, N);
    k_scan1<<<B1, 256>>>(N);
    k_scan2<<<1, 64>>>(B1, E, N);
    k_scatter<<<(E + 255) / 256, 256>>>(ei, E);
    k_acc1<<<1184, 512>>>(Wmu, Wls, b1, asmu, admu, asls, adls, N);
    k_acc2<<<1184, 512>>>(bmu, bls, out, N);
}